// round 2
// baseline (speedup 1.0000x reference)
#include <cuda_runtime.h>
#include <cstdint>
#include <math.h>

// Problem dims
#define BB 4
#define SS 2048
#define DD 768
#define HH 12
#define DKK 64

static const long long OUT_ELEMS  = (long long)BB * SS * DD;          // 6291456
static const long long ATTN_ELEMS = (long long)BB * HH * SS * SS;     // 201326592

// Scratch (device globals: allowed; no runtime allocation)
__device__ float g_q[BB * HH * SS * DKK];
__device__ float g_k[BB * HH * SS * DKK];
__device__ float g_v[BB * HH * SS * DKK];
__device__ float g_ctx[BB * SS * DD];
__device__ float g_pre[BB * SS * DD];
__device__ float g_attn_fb[(long long)BB * HH * SS * SS]; // fallback if attn not in d_out
__device__ int   g_mask_is_int32;

// ---------------------------------------------------------------------------
// Detect mask dtype: if the pad buffer is int32 (0/1 per element), every
// 32-bit word is <= 1. If it's packed bytes (bool/uint8), random 0/1 bytes
// make words like 0x00010001 — values > 1 appear almost surely in 4096 words.
// ---------------------------------------------------------------------------
__global__ void detect_mask_kernel(const unsigned int* __restrict__ pad)
{
    int is_int = 1;
    for (int i = 0; i < 4096; i++) {
        if (pad[i] > 1u) { is_int = 0; break; }
    }
    g_mask_is_int32 = is_int;
}

// ---------------------------------------------------------------------------
// Projection / output GEMM:  Y = X[8192,768] @ W[768,768] + bias (+resid)
// MODE 0/1/2: write q/k/v in [B,H,S,DK] layout. MODE 3: X=g_ctx, +resid -> g_pre
// BM=128, BN=64, BK=16, 256 threads, 8x4 per thread.
// ---------------------------------------------------------------------------
template <int MODE>
__global__ void __launch_bounds__(256) gemm768_kernel(
    const float* __restrict__ Xext, const float* __restrict__ W,
    const float* __restrict__ bias, const float* __restrict__ resid)
{
    const float* X = (MODE == 3) ? g_ctx : Xext;
    float* Y = (MODE == 0) ? g_q : (MODE == 1) ? g_k : (MODE == 2) ? g_v : g_pre;

    __shared__ float As[16][129];  // [k][m] transposed, padded
    __shared__ float Bs[16][64];

    const int tid  = threadIdx.x;
    const int m0   = blockIdx.y * 128;
    const int n0   = blockIdx.x * 64;
    const int trow = (tid / 16) * 8;
    const int tcol = (tid % 16) * 4;

    float acc[8][4] = {};

    for (int k0 = 0; k0 < DD; k0 += 16) {
        // A tile 128x16 -> transposed store
        #pragma unroll
        for (int t = 0; t < 2; t++) {
            int e = (tid + t * 256) * 4;
            int r = e / 16, c = e % 16;
            float4 v = *reinterpret_cast<const float4*>(X + (size_t)(m0 + r) * DD + k0 + c);
            As[c + 0][r] = v.x; As[c + 1][r] = v.y; As[c + 2][r] = v.z; As[c + 3][r] = v.w;
        }
        // B tile 16x64
        {
            int e = tid * 4;
            int r = e / 64, c = e % 64;
            *reinterpret_cast<float4*>(&Bs[r][c]) =
                *reinterpret_cast<const float4*>(W + (size_t)(k0 + r) * DD + n0 + c);
        }
        __syncthreads();
        #pragma unroll
        for (int kk = 0; kk < 16; kk++) {
            float a[8], b[4];
            #pragma unroll
            for (int i = 0; i < 8; i++) a[i] = As[kk][trow + i];
            #pragma unroll
            for (int j = 0; j < 4; j++) b[j] = Bs[kk][tcol + j];
            #pragma unroll
            for (int i = 0; i < 8; i++)
                #pragma unroll
                for (int j = 0; j < 4; j++) acc[i][j] += a[i] * b[j];
        }
        __syncthreads();
    }

    #pragma unroll
    for (int i = 0; i < 8; i++) {
        int r = m0 + trow + i;
        #pragma unroll
        for (int j = 0; j < 4; j++) {
            int c = n0 + tcol + j;
            float v = acc[i][j] + bias[c];
            if (MODE <= 2) {
                int b_ = r / SS, s = r % SS;
                int h = c / DKK, d = c % DKK;
                Y[(((size_t)b_ * HH + h) * SS + s) * DKK + d] = v;
            } else {
                v += resid[(size_t)r * DD + c];
                Y[(size_t)r * DD + c] = v;
            }
        }
    }
}

// ---------------------------------------------------------------------------
// Scores: per (b,h): S[q,k] = (q . k) / 8, masked. 128x128 tile, K=64.
// ---------------------------------------------------------------------------
__global__ void __launch_bounds__(256) scores_kernel(
    const void* __restrict__ pad, float* __restrict__ attn_ext)
{
    float* attn = attn_ext ? attn_ext : g_attn_fb;
    extern __shared__ float smem[];
    float (*Qs)[129] = reinterpret_cast<float(*)[129]>(smem);               // [64][129]
    float (*Ks)[129] = reinterpret_cast<float(*)[129]>(smem + 64 * 129);    // [64][129]

    const int bh = blockIdx.z;
    const int b_ = bh / HH;
    const int q0 = blockIdx.y * 128;
    const int k0 = blockIdx.x * 128;
    const int tid = threadIdx.x;
    const int mask_int = g_mask_is_int32;

    const float* qp = g_q + ((size_t)bh * SS + q0) * DKK;
    const float* kp = g_k + ((size_t)bh * SS + k0) * DKK;

    // load 128x64 q/k tiles, transposed ([d][row])
    #pragma unroll
    for (int t = 0; t < 8; t++) {
        int e = (tid + t * 256) * 4;
        int r = e / 64, c = e % 64;
        float4 v = *reinterpret_cast<const float4*>(qp + (size_t)r * DKK + c);
        Qs[c + 0][r] = v.x; Qs[c + 1][r] = v.y; Qs[c + 2][r] = v.z; Qs[c + 3][r] = v.w;
        float4 w = *reinterpret_cast<const float4*>(kp + (size_t)r * DKK + c);
        Ks[c + 0][r] = w.x; Ks[c + 1][r] = w.y; Ks[c + 2][r] = w.z; Ks[c + 3][r] = w.w;
    }
    __syncthreads();

    const int trow = (tid / 16) * 8;
    const int tcol = (tid % 16) * 8;
    float acc[8][8] = {};
    #pragma unroll
    for (int kk = 0; kk < 64; kk++) {
        float a[8], b[8];
        #pragma unroll
        for (int i = 0; i < 8; i++) a[i] = Qs[kk][trow + i];
        #pragma unroll
        for (int j = 0; j < 8; j++) b[j] = Ks[kk][tcol + j];
        #pragma unroll
        for (int i = 0; i < 8; i++)
            #pragma unroll
            for (int j = 0; j < 8; j++) acc[i][j] += a[i] * b[j];
    }

    const size_t base = (size_t)bh * SS * SS;
    #pragma unroll
    for (int i = 0; i < 8; i++) {
        int qr = q0 + trow + i;
        const size_t midx = ((size_t)b_ * SS + qr) * SS + k0 + tcol;
        int m[8];
        if (mask_int) {
            const int4* pi = reinterpret_cast<const int4*>((const int*)pad + midx);
            int4 a4 = pi[0], b4 = pi[1];
            m[0] = a4.x; m[1] = a4.y; m[2] = a4.z; m[3] = a4.w;
            m[4] = b4.x; m[5] = b4.y; m[6] = b4.z; m[7] = b4.w;
        } else {
            unsigned long long mrow =
                *reinterpret_cast<const unsigned long long*>((const unsigned char*)pad + midx);
            #pragma unroll
            for (int j = 0; j < 8; j++) m[j] = (int)((mrow >> (8 * j)) & 0xffull);
        }
        float* orow = attn + base + (size_t)qr * SS + k0 + tcol;
        #pragma unroll
        for (int j = 0; j < 8; j++) {
            float v = acc[i][j] * 0.125f;
            if (m[j]) v = -1e9f;
            orow[j] = v;
        }
    }
}

// ---------------------------------------------------------------------------
// Row softmax over 2048, one block per row, in-place.
// ---------------------------------------------------------------------------
__global__ void __launch_bounds__(256) softmax_kernel(float* __restrict__ attn_ext)
{
    float* attn = attn_ext ? attn_ext : g_attn_fb;
    const size_t row = blockIdx.x;
    float* p = attn + row * SS;
    const int tid = threadIdx.x;

    __shared__ float red[8];
    float vals[8];
    float mx = -INFINITY;
    #pragma unroll
    for (int t = 0; t < 8; t++) { vals[t] = p[tid + t * 256]; mx = fmaxf(mx, vals[t]); }
    #pragma unroll
    for (int o = 16; o; o >>= 1) mx = fmaxf(mx, __shfl_xor_sync(~0u, mx, o));
    if ((tid & 31) == 0) red[tid >> 5] = mx;
    __syncthreads();
    mx = red[0];
    #pragma unroll
    for (int w = 1; w < 8; w++) mx = fmaxf(mx, red[w]);
    __syncthreads();

    float sum = 0.f;
    #pragma unroll
    for (int t = 0; t < 8; t++) { vals[t] = __expf(vals[t] - mx); sum += vals[t]; }
    #pragma unroll
    for (int o = 16; o; o >>= 1) sum += __shfl_xor_sync(~0u, sum, o);
    if ((tid & 31) == 0) red[tid >> 5] = sum;
    __syncthreads();
    sum = 0.f;
    #pragma unroll
    for (int w = 0; w < 8; w++) sum += red[w];
    const float inv = 1.0f / sum;
    #pragma unroll
    for (int t = 0; t < 8; t++) p[tid + t * 256] = vals[t] * inv;
}

// ---------------------------------------------------------------------------
// Context: per (b,h): ctx[q,d] = attn[q,:] @ v[:,d]. BM=128, BN=64, BK=64.
// Writes into [B,S,H*DV] layout.
// ---------------------------------------------------------------------------
__global__ void __launch_bounds__(256) context_kernel(const float* __restrict__ attn_ext)
{
    const float* attn = attn_ext ? attn_ext : g_attn_fb;
    extern __shared__ float smem[];
    float (*Ast)[129] = reinterpret_cast<float(*)[129]>(smem);            // [64][129]
    float (*Vs)[64]   = reinterpret_cast<float(*)[64]>(smem + 64 * 129);  // [64][64]

    const int bh = blockIdx.y;
    const int q0 = blockIdx.x * 128;
    const int tid = threadIdx.x;
    const int trow = (tid / 16) * 8;
    const int tcol = (tid % 16) * 4;

    const float* ap = attn + ((size_t)bh * SS + q0) * SS;
    const float* vp = g_v + (size_t)bh * SS * DKK;

    float acc[8][4] = {};
    for (int k0 = 0; k0 < SS; k0 += 64) {
        #pragma unroll
        for (int t = 0; t < 8; t++) {
            int e = (tid + t * 256) * 4;
            int r = e / 64, c = e % 64;
            float4 v = *reinterpret_cast<const float4*>(ap + (size_t)r * SS + k0 + c);
            Ast[c + 0][r] = v.x; Ast[c + 1][r] = v.y; Ast[c + 2][r] = v.z; Ast[c + 3][r] = v.w;
        }
        #pragma unroll
        for (int t = 0; t < 4; t++) {
            int e = (tid + t * 256) * 4;
            int r = e / 64, c = e % 64;
            *reinterpret_cast<float4*>(&Vs[r][c]) =
                *reinterpret_cast<const float4*>(vp + (size_t)(k0 + r) * DKK + c);
        }
        __syncthreads();
        #pragma unroll
        for (int kk = 0; kk < 64; kk++) {
            float a[8], b[4];
            #pragma unroll
            for (int i = 0; i < 8; i++) a[i] = Ast[kk][trow + i];
            #pragma unroll
            for (int j = 0; j < 4; j++) b[j] = Vs[kk][tcol + j];
            #pragma unroll
            for (int i = 0; i < 8; i++)
                #pragma unroll
                for (int j = 0; j < 4; j++) acc[i][j] += a[i] * b[j];
        }
        __syncthreads();
    }

    const int b_ = bh / HH, h = bh % HH;
    #pragma unroll
    for (int i = 0; i < 8; i++) {
        int s = q0 + trow + i;
        #pragma unroll
        for (int j = 0; j < 4; j++)
            g_ctx[((size_t)b_ * SS + s) * DD + h * DKK + tcol + j] = acc[i][j];
    }
}

// ---------------------------------------------------------------------------
// LayerNorm over D=768, one block per row.
// ---------------------------------------------------------------------------
__global__ void __launch_bounds__(256) ln_kernel(
    const float* __restrict__ lg, const float* __restrict__ lb, float* __restrict__ out)
{
    const size_t row = blockIdx.x;
    const float* x = g_pre + row * DD;
    const int tid = threadIdx.x;
    __shared__ float red[8];

    float v[3];
    float s = 0.f;
    #pragma unroll
    for (int t = 0; t < 3; t++) { v[t] = x[tid + t * 256]; s += v[t]; }
    #pragma unroll
    for (int o = 16; o; o >>= 1) s += __shfl_xor_sync(~0u, s, o);
    if ((tid & 31) == 0) red[tid >> 5] = s;
    __syncthreads();
    s = 0.f;
    #pragma unroll
    for (int w = 0; w < 8; w++) s += red[w];
    const float mu = s * (1.0f / DD);
    __syncthreads();

    float var = 0.f;
    #pragma unroll
    for (int t = 0; t < 3; t++) { float d = v[t] - mu; var += d * d; }
    #pragma unroll
    for (int o = 16; o; o >>= 1) var += __shfl_xor_sync(~0u, var, o);
    if ((tid & 31) == 0) red[tid >> 5] = var;
    __syncthreads();
    var = 0.f;
    #pragma unroll
    for (int w = 0; w < 8; w++) var += red[w];
    const float inv = rsqrtf(var * (1.0f / DD) + 1e-5f);

    #pragma unroll
    for (int t = 0; t < 3; t++) {
        int c = tid + t * 256;
        out[row * DD + c] = (v[t] - mu) * inv * lg[c] + lb[c];
    }
}

// ---------------------------------------------------------------------------
extern "C" void kernel_launch(void* const* d_in, const int* in_sizes, int n_in,
                              void* d_out, int out_size)
{
    const float* Q  = (const float*)d_in[0];
    const float* K  = (const float*)d_in[1];
    const float* V  = (const float*)d_in[2];
    const void*  pad = d_in[3];
    const float* Wq = (const float*)d_in[4];
    const float* bq = (const float*)d_in[5];
    const float* Wk = (const float*)d_in[6];
    const float* bk = (const float*)d_in[7];
    const float* Wv = (const float*)d_in[8];
    const float* bv = (const float*)d_in[9];
    const float* Wo = (const float*)d_in[10];
    const float* bo = (const float*)d_in[11];
    const float* lg = (const float*)d_in[12];
    const float* lb = (const float*)d_in[13];
    float* out = (float*)d_out;

    // If d_out holds (out, attn) concatenated, write attn straight into it.
    float* attn = ((long long)out_size >= OUT_ELEMS + ATTN_ELEMS) ? (out + OUT_ELEMS)
                                                                  : nullptr; // use g_attn_fb

    const int SCORES_SMEM = 2 * 64 * 129 * 4;               // 66048
    const int CTX_SMEM    = (64 * 129 + 64 * 64) * 4;       // 49408
    cudaFuncSetAttribute(scores_kernel, cudaFuncAttributeMaxDynamicSharedMemorySize, SCORES_SMEM);
    cudaFuncSetAttribute(context_kernel, cudaFuncAttributeMaxDynamicSharedMemorySize, CTX_SMEM);

    detect_mask_kernel<<<1, 1>>>((const unsigned int*)pad);

    dim3 gp(DD / 64, (BB * SS) / 128);          // (12, 64)
    gemm768_kernel<0><<<gp, 256>>>(Q, Wq, bq, nullptr);
    gemm768_kernel<1><<<gp, 256>>>(K, Wk, bk, nullptr);
    gemm768_kernel<2><<<gp, 256>>>(V, Wv, bv, nullptr);

    dim3 gs(SS / 128, SS / 128, BB * HH);       // (16, 16, 48)
    scores_kernel<<<gs, 256, SCORES_SMEM>>>(pad, attn);

    softmax_kernel<<<BB * HH * SS, 256>>>(attn);

    dim3 gc(SS / 128, BB * HH);                 // (16, 48)
    context_kernel<<<gc, 256, CTX_SMEM>>>(attn);

    gemm768_kernel<3><<<gp, 256>>>(nullptr, Wo, bo, Q);

    ln_kernel<<<BB * SS, 256>>>(lg, lb, out);
}